// round 14
// baseline (speedup 1.0000x reference)
#include <cuda_runtime.h>
#include <cuda_fp16.h>
#include <mma.h>
#include <cstdint>
#include <math.h>

using namespace nvcuda;

#define NB 128   // batch
#define NS 100   // seq len
#define NM 50    // memory slots
#define ND 128   // dim
#define T  384   // threads: 256 compute + 128 mem
#define AS 52    // padded attn row stride (floats, 16B-aligned rows)

#define NROW (NB * NS)     // 12800 (b,s) rows
#define RPB  32            // rows per precompute block

// Scratch: attention weights, qe@W1b (NO bias), fused M = W2@[er|ad], bias
__device__ float g_attn[NB * NS * NM];
__device__ float g_q1[NB * NS * ND];
__device__ __half g_M[ND * 2 * ND];     // [k][j], j in 0..255 (e then a)
__device__ float  g_bias[2 * ND];       // b2@[er|ad] + [er_b|ad_b]

#define BAR256()         asm volatile("bar.sync 1, 256;" ::: "memory")

__device__ __forceinline__ float tanh_fast(float x) {
    float y;
    asm("tanh.approx.f32 %0, %1;" : "=f"(y) : "f"(x));
    return y;
}
__device__ __forceinline__ float sigmoid_fast(float x) {
    return fmaf(0.5f, tanh_fast(0.5f * x), 0.5f);
}
__device__ __forceinline__ uint2 f4_to_h4(float4 w) {
    const __half2 h01 = __floats2half2_rn(w.x, w.y);
    const __half2 h23 = __floats2half2_rn(w.z, w.w);
    uint2 o;
    o.x = *(const unsigned*)&h01;
    o.y = *(const unsigned*)&h23;
    return o;
}

// ---------------------------------------------------------------------------
// K0: combine W2 with er/ad:  M[k][j] = sum_i W2[k][i]*E[i][j],
//     bias[j] = sum_i b2[i]*E[i][j] + eb[j].   grid=128 (k), block=256 (j).
// ---------------------------------------------------------------------------
__global__ __launch_bounds__(256, 1)
void combine_kernel(const float* __restrict__ vu_w2,
                    const float* __restrict__ vu_b2,
                    const float* __restrict__ er_w,
                    const float* __restrict__ er_b,
                    const float* __restrict__ ad_w,
                    const float* __restrict__ ad_b) {
    __shared__ float w2row[ND];
    const int k = blockIdx.x;
    const int j = threadIdx.x;
    for (int i = j; i < ND; i += 256) w2row[i] = vu_w2[k * ND + i];
    __syncthreads();
    const float* E = (j < ND) ? er_w : ad_w;
    const int jj = j & (ND - 1);
    float acc = 0.f;
#pragma unroll 8
    for (int i = 0; i < ND; i++) acc = fmaf(w2row[i], E[i * ND + jj], acc);
    g_M[k * 2 * ND + j] = __float2half_rn(acc);
    if (k == 0) {
        float bacc = (j < ND) ? er_b[jj] : ad_b[jj];
        for (int i = 0; i < ND; i++) bacc = fmaf(vu_b2[i], E[i * ND + jj], bacc);
        g_bias[j] = bacc;
    }
}

// ---------------------------------------------------------------------------
// K1 (wmma rewrite): per 32-row block, everything fp16 in smem;
//   logits  = wmma 32x64 (key padded 50->64 with zero rows), softmax fp32;
//   q1      = wmma 32x128, stored WITHOUT bias (recurrent adds b1).
// smem ~66KB -> 3 blocks/SM -> grid 400 in ~1 wave.
// ---------------------------------------------------------------------------
#define Q_KEYH 0                        // 64x128 half  = 4096 float slots
#define Q_W1BH 4096                     // 128x128 half = 8192 float slots
#define Q_QEH  12288                    // 32x128 half  = 2048 float slots
#define Q_LOG  14336                    // 32x64 fp32   = 2048 float slots
#define Q_IDS  16384                    // 32 ints
#define Q_TOTF 16416
#define PRE_SMEM_BYTES (Q_TOTF * 4)

__global__ __launch_bounds__(256, 3)
void precompute_kernel(const int* __restrict__ qseq,
                       const float* __restrict__ emb,
                       const float* __restrict__ keym,
                       const float* __restrict__ vu_w1) {
    extern __shared__ float ps[];
    __half* sKeyH = (__half*)(ps + Q_KEYH);
    __half* sW1bH = (__half*)(ps + Q_W1BH);
    __half* sQeH  = (__half*)(ps + Q_QEH);
    float*  sLog  = ps + Q_LOG;
    int*    sIds  = (int*)(ps + Q_IDS);

    const int t  = threadIdx.x;
    const int r0 = blockIdx.x * RPB;

    if (t < RPB) sIds[t] = qseq[r0 + t];

    // key -> fp16 (rows 50..63 zero-filled)
    for (int i = t; i < 64 * 32; i += 256) {        // float4 groups
        const int m = i >> 5;
        float4 w = {0.f, 0.f, 0.f, 0.f};
        if (m < NM) w = ((const float4*)keym)[i];
        ((uint2*)sKeyH)[i] = f4_to_h4(w);
    }
    // w1b (rows 128..255 of vu_w1) -> fp16
    {
        const float4* src = (const float4*)(vu_w1 + ND * ND);
        for (int i = t; i < ND * 32; i += 256)
            ((uint2*)sW1bH)[i] = f4_to_h4(src[i]);
    }
    __syncthreads();   // ids visible before gather

    // qe gather -> fp16
    for (int i = t; i < RPB * 32; i += 256) {
        const int row = i >> 5, c4 = i & 31;
        const float4 q = ((const float4*)(emb + (size_t)sIds[row] * ND))[c4];
        ((uint2*)sQeH)[row * 32 + c4] = f4_to_h4(q);
    }
    __syncthreads();

    const int w = t >> 5;
    const int lid = t & 31;

    // ---- logits: 8 tiles of 16x16, one per warp ----
    {
        wmma::fragment<wmma::matrix_a, 16, 16, 16, __half, wmma::row_major> fa;
        wmma::fragment<wmma::matrix_b, 16, 16, 16, __half, wmma::col_major> fb;
        wmma::fragment<wmma::accumulator, 16, 16, 16, float> fc;
        wmma::fill_fragment(fc, 0.f);
        const int rt = w >> 2, ct = w & 3;
#pragma unroll
        for (int k = 0; k < 8; k++) {
            wmma::load_matrix_sync(fa, sQeH + rt * 16 * ND + k * 16, ND);
            wmma::load_matrix_sync(fb, sKeyH + ct * 16 * ND + k * 16, ND);
            wmma::mma_sync(fc, fa, fb, fc);
        }
        wmma::store_matrix_sync(sLog + rt * 16 * 64 + ct * 16, fc, 64,
                                wmma::mem_row_major);
    }
    __syncthreads();

    // ---- softmax (fp32, 8 warps x 4 rows, lane = m) ----
    {
        const bool hasB = (lid < NM - 32);
#pragma unroll
        for (int r = 0; r < 4; r++) {
            const int row = w * 4 + r;
            float v0 = sLog[row * 64 + lid];
            float v1 = hasB ? sLog[row * 64 + 32 + lid] : -1e30f;
            float mx = fmaxf(v0, v1);
#pragma unroll
            for (int o = 16; o; o >>= 1) mx = fmaxf(mx, __shfl_xor_sync(0xffffffffu, mx, o));
            float e0 = __expf(v0 - mx);
            float e1 = hasB ? __expf(v1 - mx) : 0.f;
            float sum = e0 + e1;
#pragma unroll
            for (int o = 16; o; o >>= 1) sum += __shfl_xor_sync(0xffffffffu, sum, o);
            const float inv = 1.f / sum;
            float* dst = g_attn + (size_t)(r0 + row) * NM;
            dst[lid] = e0 * inv;
            if (hasB) dst[lid + 32] = e1 * inv;
        }
    }

    // ---- q1 = qe @ w1b (no bias): 16 tiles, 2 per warp ----
    {
        wmma::fragment<wmma::matrix_a, 16, 16, 16, __half, wmma::row_major> fa;
        wmma::fragment<wmma::matrix_b, 16, 16, 16, __half, wmma::row_major> fb0, fb1;
        wmma::fragment<wmma::accumulator, 16, 16, 16, float> fc0, fc1;
        wmma::fill_fragment(fc0, 0.f);
        wmma::fill_fragment(fc1, 0.f);
        const int rt = w >> 2;
        const int ct0 = (w & 3) * 2;
#pragma unroll
        for (int k = 0; k < 8; k++) {
            wmma::load_matrix_sync(fa, sQeH + rt * 16 * ND + k * 16, ND);
            wmma::load_matrix_sync(fb0, sW1bH + k * 16 * ND + ct0 * 16, ND);
            wmma::load_matrix_sync(fb1, sW1bH + k * 16 * ND + (ct0 + 1) * 16, ND);
            wmma::mma_sync(fc0, fa, fb0, fc0);
            wmma::mma_sync(fc1, fa, fb1, fc1);
        }
        float* dst = g_q1 + (size_t)(r0 + rt * 16) * ND;
        wmma::store_matrix_sync(dst + ct0 * 16, fc0, ND, wmma::mem_row_major);
        wmma::store_matrix_sync(dst + (ct0 + 1) * 16, fc1, ND, wmma::mem_row_major);
    }
}

// ---------------------------------------------------------------------------
// K2: warp-specialized recurrent kernel (R12 structure; + b1 added in M-pro).
// ---------------------------------------------------------------------------
// smem layout (floats)
#define SM_W1H  0                         // 128*128 half = 8192 floats
#define SM_ATTN 8192                      // 100*52 = 5200 (padded rows)
#define SM_PA   13392                     // 1024 (A partials)
#define SM_PC   14416                     // 2 x 1024 (pre-act partials, parity)
#define SM_READ 16464                     // 128 (tail only)
#define SM_H    16592                     // 128 (tail only)
#define SM_UP   16720                     // 128 (tail only)
#define SM_BE   16848                     // 128 (bias_e)
#define SM_BA   16976                     // 128 (bias_a)
#define SM_R0   17104                     // 2 x 256 (parity x 2 halves)
#define SM_G    17616                     // 2 x 256
#define SM_C    18128                     // 2 x 2 (+4 pad)
#define SM_V    18136                     // 50*128 = 6400
#define SM_TOTF (SM_V + NM * ND)
#define SMEM_BYTES (SM_TOTF * 4)

__global__ __launch_bounds__(T, 1)
void recurrent_kernel(const int* __restrict__ qseq,
                      const float* __restrict__ emb,
                      const float* __restrict__ vu_w1,
                      const float* __restrict__ vu_b1,
                      const float* __restrict__ out_w1,
                      const float* __restrict__ out_b1,
                      const float* __restrict__ out_w2,
                      const float* __restrict__ out_b2,
                      float* __restrict__ out) {
    extern __shared__ float sm[];
    __half* sW1h = (__half*)(sm + SM_W1H);
    float* sAttn = sm + SM_ATTN;
    float* sPA   = sm + SM_PA;
    float* sPC   = sm + SM_PC;
    float* sRead = sm + SM_READ;
    float* sH    = sm + SM_H;
    float* sUp   = sm + SM_UP;
    float* sV    = sm + SM_V;

    const int b = blockIdx.x;
    const int t = threadIdx.x;

    // ---- shared init ----
    for (int i = t; i < ND * ND; i += T) sW1h[i] = __float2half_rn(vu_w1[i]);
    for (int i = t; i < NS * NM; i += T)
        sAttn[(i / NM) * AS + (i % NM)] = g_attn[b * NS * NM + i];
    for (int i = t; i < 2 * 1024; i += T) sPC[i] = 0.f;
    for (int i = t; i < 1032; i += T) sm[SM_R0 + i] = 0.f;   // r0/g/c region
    for (int i = t; i < NM * ND; i += T) sV[i] = 0.f;
    if (t < ND) {
        sm[SM_BE + t] = g_bias[t];
        sm[SM_BA + t] = g_bias[ND + t];
    }

    // ---- compute-role registers: fused matrix M as packed half2 ----
    const int lid = t & 31;
    const int jq = t & 63;            // output quad (256 outputs / 4)
    const int ks = (t >> 6) & 3;      // k-slice of 32
    __half2 mh01[32], mh23[32];
    if (t < 256) {
#pragma unroll
        for (int kk = 0; kk < 32; kk++) {
            const uint2 raw = *(const uint2*)(g_M + (ks * 32 + kk) * 2 * ND + jq * 4);
            mh01[kk] = *(const __half2*)&raw.x;
            mh23[kk] = *(const __half2*)&raw.y;
        }
    }
    // mem-role mapping: 2 d-columns, half m-range
    const int u2 = t - 256;           // 0..127
    const int hh = u2 >> 6;           // m-half: 0 -> m 0..23, 1 -> m 24..49
    const int c2 = (u2 & 63) * 2;     // d-column pair

    // compute stage mappings
    const int j4 = (t & 31) * 4;
    const int kg = (t >> 5) & 7;              // compute warp id
    const int kownA = kg * 16 + (lid & 15);   // A slice (16 k per warp)
    const int kownC = ks * 32 + lid;          // M slice (32 k per warp)
    const float b1reg = (t < 256) ? vu_b1[kownC] : 0.f;   // q1 bias (moved here)

    __syncthreads();

    const float* q1b = g_q1 + b * NS * ND;

    for (int s = 0; s < NS; s++) {
        const int par  = s & 1;         // sPC written; r0/g/c consumed
        const int parm = (s + 1) & 1;   // sPC from prev step; r0/g/c written

        if (t < 256) {
            const float q1f = q1b[s * ND + kownC] + b1reg;
            const float* pc = sPC + parm * 1024;

            // ---- A prologue: reconstruct e/a at kownA, then read value ----
            float rd;
            {
                float pe = sm[SM_BE + kownA];
                float pa = sm[SM_BA + kownA];
#pragma unroll
                for (int g = 0; g < 4; g++) {
                    pe += pc[g * 256 + kownA];
                    pa += pc[g * 256 + 128 + kownA];
                }
                const float e = sigmoid_fast(pe);
                const float a = tanh_fast(pa);
                const float r0 = sm[SM_R0 + par * 256 + kownA]
                               + sm[SM_R0 + par * 256 + 128 + kownA];
                const float gg = sm[SM_G + par * 256 + kownA]
                               + sm[SM_G + par * 256 + 128 + kownA];
                const float cc = sm[SM_C + par * 2] + sm[SM_C + par * 2 + 1];
                rd = fmaf(cc, a, fmaf(-e, gg, r0));
            }
            // ---- A GEMV (fp16): x as dup'd half2 broadcast via shfl ----
            {
                const __half2 rh2 = __float2half2_rn(rd);
                const unsigned ru = *(const unsigned*)&rh2;
                __half2 acc01 = __floats2half2_rn(0.f, 0.f);
                __half2 acc23 = acc01;
                const __half* wrow = sW1h + (kg * 16) * ND + j4;
#pragma unroll
                for (int i = 0; i < 16; i++) {
                    const unsigned xs = __shfl_sync(0xffffffffu, ru, i);
                    const __half2 xh = *(const __half2*)&xs;
                    const uint2 raw = *(const uint2*)(wrow + i * ND);
                    acc01 = __hfma2(xh, *(const __half2*)&raw.x, acc01);
                    acc23 = __hfma2(xh, *(const __half2*)&raw.y, acc23);
                }
                const float2 f01 = __half22float2(acc01);
                const float2 f23 = __half22float2(acc23);
                float4 o = {f01.x, f01.y, f23.x, f23.y};
                *(float4*)(sPA + kg * ND + j4) = o;
            }
            BAR256();

            // ---- M prologue: h[kownC] = tanh(q1 + b1 + sum partials) ----
            float hv;
            {
                float v = q1f;
#pragma unroll
                for (int g = 0; g < 8; g++) v += sPA[g * ND + kownC];
                hv = tanh_fast(v);
            }
            // ---- M GEMV (fp16): 256 pre-act outputs ----
            {
                const __half2 hh2 = __float2half2_rn(hv);
                const unsigned hu = *(const unsigned*)&hh2;
                __half2 acc01 = __floats2half2_rn(0.f, 0.f);
                __half2 acc23 = acc01;
#pragma unroll
                for (int i = 0; i < 32; i++) {
                    const unsigned xs = __shfl_sync(0xffffffffu, hu, i);
                    const __half2 xh = *(const __half2*)&xs;
                    acc01 = __hfma2(xh, mh01[i], acc01);
                    acc23 = __hfma2(xh, mh23[i], acc23);
                }
                const float2 p01 = __half22float2(acc01);
                const float2 p23 = __half22float2(acc23);
                float4 o = {p01.x, p01.y, p23.x, p23.y};
                *(float4*)(sPC + par * 1024 + ks * 256 + jq * 4) = o;
            }
        } else {
            // ---- mem warps: 2 columns x half m-range ----
            const int moff = hh ? 24 : 0;
            const float* wub = sAttn + (s ? (s - 1) * AS : 0) + moff;
            const float* wsb = sAttn + s * AS + moff;
            const float* wrb = sAttn + ((s + 1 < NS) ? (s + 1) : (NS - 1)) * AS + moff;
            float2 ev, av;
            if (s == 0) {
                ev.x = ev.y = av.x = av.y = 0.f;
            } else {
                const float* pc = sPC + parm * 1024;
                float2 pe = *(const float2*)(sm + SM_BE + c2);
                float2 pa = *(const float2*)(sm + SM_BA + c2);
#pragma unroll
                for (int g = 0; g < 4; g++) {
                    const float2 q = *(const float2*)(pc + g * 256 + c2);
                    const float2 r = *(const float2*)(pc + g * 256 + 128 + c2);
                    pe.x += q.x; pe.y += q.y;
                    pa.x += r.x; pa.y += r.y;
                }
                ev.x = sigmoid_fast(pe.x); ev.y = sigmoid_fast(pe.y);
                av.x = tanh_fast(pa.x);    av.y = tanh_fast(pa.y);
            }
            const float nex = -ev.x, ney = -ev.y;
            float2 r0v = {0.f, 0.f}, gv = {0.f, 0.f};
            float cacc = 0.f;

#define MEM2(wum, wsm, wrm, m) { \
    float2 v = *(float2*)(sV + (m) * ND + c2); \
    v.x = fmaf(wum, fmaf(nex, v.x, av.x), v.x); \
    v.y = fmaf(wum, fmaf(ney, v.y, av.y), v.y); \
    *(float2*)(sV + (m) * ND + c2) = v; \
    const float px = (wrm) * v.x, py = (wrm) * v.y; \
    r0v.x += px; r0v.y += py; \
    gv.x = fmaf(wsm, px, gv.x); gv.y = fmaf(wsm, py, gv.y); \
    cacc = fmaf(wrm, wsm, cacc); }

#pragma unroll
            for (int q = 0; q < 6; q++) {
                const float4 wu4 = *(const float4*)(wub + q * 4);
                const float4 ws4 = *(const float4*)(wsb + q * 4);
                const float4 wr4 = *(const float4*)(wrb + q * 4);
                MEM2(wu4.x, ws4.x, wr4.x, moff + q * 4 + 0)
                MEM2(wu4.y, ws4.y, wr4.y, moff + q * 4 + 1)
                MEM2(wu4.z, ws4.z, wr4.z, moff + q * 4 + 2)
                MEM2(wu4.w, ws4.w, wr4.w, moff + q * 4 + 3)
            }
            if (hh) {
                const float2 wu2 = *(const float2*)(wub + 24);
                const float2 ws2 = *(const float2*)(wsb + 24);
                const float2 wr2 = *(const float2*)(wrb + 24);
                MEM2(wu2.x, ws2.x, wr2.x, 48)
                MEM2(wu2.y, ws2.y, wr2.y, 49)
            }
#undef MEM2
            *(float2*)(sm + SM_R0 + parm * 256 + hh * 128 + c2) = r0v;
            *(float2*)(sm + SM_G  + parm * 256 + hh * 128 + c2) = gv;
            if ((u2 & 63) == 0) sm[SM_C + parm * 2 + hh] = cacc;
        }
        __syncthreads();
    }

    // ---- tail: read_out = w_99 . v_100 via the same identity ----
    if (t < ND) {
        const float* pc = sPC + 1024;       // parity of s=99
        float pe = sm[SM_BE + t];
        float pa = sm[SM_BA + t];
#pragma unroll
        for (int g = 0; g < 4; g++) {
            pe += pc[g * 256 + t];
            pa += pc[g * 256 + 128 + t];
        }
        const float e = sigmoid_fast(pe);
        const float a = tanh_fast(pa);
        const float r0 = sm[SM_R0 + t] + sm[SM_R0 + 128 + t];   // parity 0
        const float gg = sm[SM_G + t] + sm[SM_G + 128 + t];
        const float cc = sm[SM_C] + sm[SM_C + 1];
        sRead[t] = fmaf(cc, a, fmaf(-e, gg, r0));
        const int qi = qseq[b * NS + (NS - 1)];
        sUp[t] = emb[qi * ND + t];   // qe_last
    }
    __syncthreads();

    // ---- output head (fp32 weights from global; one-shot) ----
    if (t < 256) {
        const float* pin = (kg < 4) ? sRead : (sUp - ND);
        float4 acc = {0.f, 0.f, 0.f, 0.f};
#pragma unroll
        for (int i = 0; i < 32; i++) {
            const int k = kg * 32 + i;
            const float x = pin[k];
            const float4 w = *(const float4*)(out_w1 + k * ND + j4);
            acc.x = fmaf(x, w.x, acc.x);
            acc.y = fmaf(x, w.y, acc.y);
            acc.z = fmaf(x, w.z, acc.z);
            acc.w = fmaf(x, w.w, acc.w);
        }
        *(float4*)(sPA + kg * ND + j4) = acc;
    }
    __syncthreads();
    if (t < ND) {
        float v = out_b1[t];
#pragma unroll
        for (int g = 0; g < 8; g++) v += sPA[g * ND + t];
        sH[t] = fmaxf(v, 0.f) * out_w2[t];
    }
    __syncthreads();
    if (t < 32) {
        float v = sH[t] + sH[t + 32] + sH[t + 64] + sH[t + 96];
#pragma unroll
        for (int o = 16; o; o >>= 1) v += __shfl_xor_sync(0xffffffffu, v, o);
        if (t == 0) out[b] = 1.f / (1.f + __expf(-(v + out_b2[0])));
    }
}

// ---------------------------------------------------------------------------
extern "C" void kernel_launch(void* const* d_in, const int* in_sizes, int n_in,
                              void* d_out, int out_size) {
    const int*   qseq   = (const int*)  d_in[0];
    // d_in[1] = answer_seq (unused by reference)
    const float* emb    = (const float*)d_in[2];
    const float* keym   = (const float*)d_in[3];
    const float* vu_w1  = (const float*)d_in[4];
    const float* vu_b1  = (const float*)d_in[5];
    const float* vu_w2  = (const float*)d_in[6];
    const float* vu_b2  = (const float*)d_in[7];
    const float* er_w   = (const float*)d_in[8];
    const float* er_b   = (const float*)d_in[9];
    const float* ad_w   = (const float*)d_in[10];
    const float* ad_b   = (const float*)d_in[11];
    const float* out_w1 = (const float*)d_in[12];
    const float* out_b1 = (const float*)d_in[13];
    const float* out_w2 = (const float*)d_in[14];
    const float* out_b2 = (const float*)d_in[15];
    float* out = (float*)d_out;

    cudaFuncSetAttribute(precompute_kernel,
                         cudaFuncAttributeMaxDynamicSharedMemorySize, PRE_SMEM_BYTES);
    cudaFuncSetAttribute(recurrent_kernel,
                         cudaFuncAttributeMaxDynamicSharedMemorySize, SMEM_BYTES);

    precompute_kernel<<<NROW / RPB, 256, PRE_SMEM_BYTES>>>(qseq, emb, keym, vu_w1);
    combine_kernel<<<ND, 256>>>(vu_w2, vu_b2, er_w, er_b, ad_w, ad_b);
    recurrent_kernel<<<NB, T, SMEM_BYTES>>>(qseq, emb, vu_w1, vu_b1,
                                            out_w1, out_b1, out_w2, out_b2, out);
}

// round 15
// speedup vs baseline: 1.0012x; 1.0012x over previous
#include <cuda_runtime.h>
#include <cuda_fp16.h>
#include <mma.h>
#include <cstdint>
#include <math.h>

using namespace nvcuda;

#define NB 128   // batch
#define NS 100   // seq len
#define NM 50    // memory slots
#define ND 128   // dim
#define T  384   // threads: 256 compute + 128 mem
#define AS 52    // padded attn row stride (floats)

// Fused matrix M = W2@[er|ad] and bias = b2@[er|ad] + [er_b|ad_b]
__device__ __half g_M[ND * 2 * ND];
__device__ float  g_bias[2 * ND];

#define BAR256()         asm volatile("bar.sync 1, 256;" ::: "memory")

__device__ __forceinline__ float tanh_fast(float x) {
    float y;
    asm("tanh.approx.f32 %0, %1;" : "=f"(y) : "f"(x));
    return y;
}
__device__ __forceinline__ float sigmoid_fast(float x) {
    return fmaf(0.5f, tanh_fast(0.5f * x), 0.5f);
}
__device__ __forceinline__ uint2 f4_to_h4(float4 w) {
    const __half2 h01 = __floats2half2_rn(w.x, w.y);
    const __half2 h23 = __floats2half2_rn(w.z, w.w);
    uint2 o;
    o.x = *(const unsigned*)&h01;
    o.y = *(const unsigned*)&h23;
    return o;
}

// ---------------------------------------------------------------------------
// K0: combine W2 with er/ad (unchanged).
// ---------------------------------------------------------------------------
__global__ __launch_bounds__(256, 1)
void combine_kernel(const float* __restrict__ vu_w2,
                    const float* __restrict__ vu_b2,
                    const float* __restrict__ er_w,
                    const float* __restrict__ er_b,
                    const float* __restrict__ ad_w,
                    const float* __restrict__ ad_b) {
    __shared__ float w2row[ND];
    const int k = blockIdx.x;
    const int j = threadIdx.x;
    for (int i = j; i < ND; i += 256) w2row[i] = vu_w2[k * ND + i];
    __syncthreads();
    const float* E = (j < ND) ? er_w : ad_w;
    const int jj = j & (ND - 1);
    float acc = 0.f;
#pragma unroll 8
    for (int i = 0; i < ND; i++) acc = fmaf(w2row[i], E[i * ND + jj], acc);
    g_M[k * 2 * ND + j] = __float2half_rn(acc);
    if (k == 0) {
        float bacc = (j < ND) ? er_b[jj] : ad_b[jj];
        for (int i = 0; i < ND; i++) bacc = fmaf(vu_b2[i], E[i * ND + jj], bacc);
        g_bias[j] = bacc;
    }
}

// ---------------------------------------------------------------------------
// Fused kernel: per-CTA prologue computes this batch element's attention
// (softmax -> sAttn) and q1 = qe@w1b (wmma -> sQ1 fp32), then runs the
// warp-specialized recurrence (R12 structure).
// ---------------------------------------------------------------------------
// Persistent smem (floats):
#define SM_ATTN 0                         // 100*52 = 5200
#define SM_Q1   5200                      // 112*128 fp32 = 14336
#define SM_LOOP 19536
// Loop-phase regions (initialized after prologue):
#define SM_W1H  19536                     // 128*128 fp16 = 8192 floats
#define SM_PA   27728                     // 1024
#define SM_PC   28752                     // 2 x 1024
#define SM_READ 30800                     // 128 (tail)
#define SM_H    30928                     // 128 (tail)
#define SM_UP   31056                     // 128 (tail)
#define SM_BE   31184                     // 128
#define SM_BA   31312                     // 128
#define SM_R0   31440                     // 2 x 256
#define SM_G    31952                     // 2 x 256
#define SM_C    32464                     // 8
#define SM_V    32472                     // 6400 -> ends 38872
// Prologue temp regions (alias loop regions, live only before init):
#define TP_KEYH 19536                     // 64x128 fp16 = 4096 floats
#define TP_W1BH 23632                     // 128x128 fp16 = 8192 floats
#define TP_QEH  31824                     // 112x128 fp16 = 7168 floats
#define TP_LOG  38992                     // 112x64 fp32 = 7168 floats
#define TP_IDS  46160                     // 128 ints
#define SM_TOTF 46288
#define SMEM_BYTES (SM_TOTF * 4)

__global__ __launch_bounds__(T, 1)
void fused_kernel(const int* __restrict__ qseq,
                  const float* __restrict__ emb,
                  const float* __restrict__ keym,
                  const float* __restrict__ vu_w1,
                  const float* __restrict__ vu_b1,
                  const float* __restrict__ out_w1,
                  const float* __restrict__ out_b1,
                  const float* __restrict__ out_w2,
                  const float* __restrict__ out_b2,
                  float* __restrict__ out) {
    extern __shared__ float sm[];
    float*  sAttn = sm + SM_ATTN;
    float*  sQ1   = sm + SM_Q1;
    __half* sW1h  = (__half*)(sm + SM_W1H);
    float*  sPA   = sm + SM_PA;
    float*  sPC   = sm + SM_PC;
    float*  sRead = sm + SM_READ;
    float*  sH    = sm + SM_H;
    float*  sUp   = sm + SM_UP;
    float*  sV    = sm + SM_V;
    __half* tKeyH = (__half*)(sm + TP_KEYH);
    __half* tW1bH = (__half*)(sm + TP_W1BH);
    __half* tQeH  = (__half*)(sm + TP_QEH);
    float*  tLog  = sm + TP_LOG;
    int*    tIds  = (int*)(sm + TP_IDS);

    const int b = blockIdx.x;
    const int t = threadIdx.x;
    const int w = t >> 5;
    const int lid = t & 31;

    // ======================= PROLOGUE: attn + q1 =======================
    if (t < NS) tIds[t] = qseq[b * NS + t];

    // key -> fp16 (rows 50..63 zero)
    for (int i = t; i < 64 * 32; i += T) {
        const int m = i >> 5;
        float4 v = {0.f, 0.f, 0.f, 0.f};
        if (m < NM) v = ((const float4*)keym)[i];
        ((uint2*)tKeyH)[i] = f4_to_h4(v);
    }
    // w1b (rows 128..255 of vu_w1) -> fp16
    {
        const float4* src = (const float4*)(vu_w1 + ND * ND);
        for (int i = t; i < ND * 32; i += T)
            ((uint2*)tW1bH)[i] = f4_to_h4(src[i]);
    }
    __syncthreads();   // ids visible

    // qe gather -> fp16 (rows 100..111 zero)
    for (int i = t; i < 112 * 32; i += T) {
        const int row = i >> 5, c4 = i & 31;
        uint2 o = {0u, 0u};
        if (row < NS) {
            const float4 q = ((const float4*)(emb + (size_t)tIds[row] * ND))[c4];
            o = f4_to_h4(q);
        }
        ((uint2*)tQeH)[i] = o;
    }
    __syncthreads();

    // logits: 7x4 tiles of 16x16 over 12 warps
    for (int tile = w; tile < 28; tile += 12) {
        const int rt = tile >> 2, ct = tile & 3;
        wmma::fragment<wmma::matrix_a, 16, 16, 16, __half, wmma::row_major> fa;
        wmma::fragment<wmma::matrix_b, 16, 16, 16, __half, wmma::col_major> fb;
        wmma::fragment<wmma::accumulator, 16, 16, 16, float> fc;
        wmma::fill_fragment(fc, 0.f);
#pragma unroll
        for (int k = 0; k < 8; k++) {
            wmma::load_matrix_sync(fa, tQeH + rt * 16 * ND + k * 16, ND);
            wmma::load_matrix_sync(fb, tKeyH + ct * 16 * ND + k * 16, ND);
            wmma::mma_sync(fc, fa, fb, fc);
        }
        wmma::store_matrix_sync(tLog + rt * 16 * 64 + ct * 16, fc, 64,
                                wmma::mem_row_major);
    }
    __syncthreads();

    // softmax rows -> sAttn (padded stride AS)
    {
        const bool hasB = (lid < NM - 32);
        for (int row = w; row < NS; row += 12) {
            float v0 = tLog[row * 64 + lid];
            float v1 = hasB ? tLog[row * 64 + 32 + lid] : -1e30f;
            float mx = fmaxf(v0, v1);
#pragma unroll
            for (int o = 16; o; o >>= 1) mx = fmaxf(mx, __shfl_xor_sync(0xffffffffu, mx, o));
            float e0 = __expf(v0 - mx);
            float e1 = hasB ? __expf(v1 - mx) : 0.f;
            float sum = e0 + e1;
#pragma unroll
            for (int o = 16; o; o >>= 1) sum += __shfl_xor_sync(0xffffffffu, sum, o);
            const float inv = 1.f / sum;
            float* dst = sAttn + row * AS;
            dst[lid] = e0 * inv;
            if (hasB) dst[lid + 32] = e1 * inv;
        }
    }

    // q1 = qe @ w1b (no bias): 7x8 tiles over 12 warps -> sQ1 fp32
    for (int tile = w; tile < 56; tile += 12) {
        const int rt = tile >> 3, ct = tile & 7;
        wmma::fragment<wmma::matrix_a, 16, 16, 16, __half, wmma::row_major> fa;
        wmma::fragment<wmma::matrix_b, 16, 16, 16, __half, wmma::row_major> fb;
        wmma::fragment<wmma::accumulator, 16, 16, 16, float> fc;
        wmma::fill_fragment(fc, 0.f);
#pragma unroll
        for (int k = 0; k < 8; k++) {
            wmma::load_matrix_sync(fa, tQeH + rt * 16 * ND + k * 16, ND);
            wmma::load_matrix_sync(fb, tW1bH + k * 16 * ND + ct * 16, ND);
            wmma::mma_sync(fc, fa, fb, fc);
        }
        wmma::store_matrix_sync(sQ1 + rt * 16 * ND + ct * 16, fc, ND,
                                wmma::mem_row_major);
    }
    __syncthreads();   // prologue reads done; temps may be overwritten

    // ======================= LOOP-REGION INIT =======================
    for (int i = t; i < ND * ND; i += T) sW1h[i] = __float2half_rn(vu_w1[i]);
    for (int i = t; i < 2 * 1024; i += T) sPC[i] = 0.f;
    for (int i = t; i < 1032; i += T) sm[SM_R0 + i] = 0.f;
    for (int i = t; i < NM * ND; i += T) sV[i] = 0.f;
    if (t < ND) {
        sm[SM_BE + t] = g_bias[t];
        sm[SM_BA + t] = g_bias[ND + t];
    }

    // compute-role registers: fused matrix M as packed half2
    const int jq = t & 63;
    const int ks = (t >> 6) & 3;
    __half2 mh01[32], mh23[32];
    if (t < 256) {
#pragma unroll
        for (int kk = 0; kk < 32; kk++) {
            const uint2 raw = *(const uint2*)(g_M + (ks * 32 + kk) * 2 * ND + jq * 4);
            mh01[kk] = *(const __half2*)&raw.x;
            mh23[kk] = *(const __half2*)&raw.y;
        }
    }
    const int u2 = t - 256;
    const int hh = u2 >> 6;
    const int c2 = (u2 & 63) * 2;

    const int j4 = (t & 31) * 4;
    const int kg = (t >> 5) & 7;
    const int kownA = kg * 16 + (lid & 15);
    const int kownC = ks * 32 + lid;
    const float b1reg = (t < 256) ? vu_b1[kownC] : 0.f;

    __syncthreads();

    // ======================= RECURRENCE =======================
    for (int s = 0; s < NS; s++) {
        const int par  = s & 1;
        const int parm = (s + 1) & 1;

        if (t < 256) {
            const float q1f = sQ1[s * ND + kownC] + b1reg;
            const float* pc = sPC + parm * 1024;

            // A prologue: reconstruct e/a at kownA, then read value
            float rd;
            {
                float pe = sm[SM_BE + kownA];
                float pa = sm[SM_BA + kownA];
#pragma unroll
                for (int g = 0; g < 4; g++) {
                    pe += pc[g * 256 + kownA];
                    pa += pc[g * 256 + 128 + kownA];
                }
                const float e = sigmoid_fast(pe);
                const float a = tanh_fast(pa);
                const float r0 = sm[SM_R0 + par * 256 + kownA]
                               + sm[SM_R0 + par * 256 + 128 + kownA];
                const float gg = sm[SM_G + par * 256 + kownA]
                               + sm[SM_G + par * 256 + 128 + kownA];
                const float cc = sm[SM_C + par * 2] + sm[SM_C + par * 2 + 1];
                rd = fmaf(cc, a, fmaf(-e, gg, r0));
            }
            // A GEMV (fp16)
            {
                const __half2 rh2 = __float2half2_rn(rd);
                const unsigned ru = *(const unsigned*)&rh2;
                __half2 acc01 = __floats2half2_rn(0.f, 0.f);
                __half2 acc23 = acc01;
                const __half* wrow = sW1h + (kg * 16) * ND + j4;
#pragma unroll
                for (int i = 0; i < 16; i++) {
                    const unsigned xs = __shfl_sync(0xffffffffu, ru, i);
                    const __half2 xh = *(const __half2*)&xs;
                    const uint2 raw = *(const uint2*)(wrow + i * ND);
                    acc01 = __hfma2(xh, *(const __half2*)&raw.x, acc01);
                    acc23 = __hfma2(xh, *(const __half2*)&raw.y, acc23);
                }
                const float2 f01 = __half22float2(acc01);
                const float2 f23 = __half22float2(acc23);
                float4 o = {f01.x, f01.y, f23.x, f23.y};
                *(float4*)(sPA + kg * ND + j4) = o;
            }
            BAR256();

            // M prologue: h[kownC] = tanh(q1 + b1 + sum partials)
            float hv;
            {
                float v = q1f;
#pragma unroll
                for (int g = 0; g < 8; g++) v += sPA[g * ND + kownC];
                hv = tanh_fast(v);
            }
            // M GEMV (fp16): 256 pre-act outputs
            {
                const __half2 hh2 = __float2half2_rn(hv);
                const unsigned hu = *(const unsigned*)&hh2;
                __half2 acc01 = __floats2half2_rn(0.f, 0.f);
                __half2 acc23 = acc01;
#pragma unroll
                for (int i = 0; i < 32; i++) {
                    const unsigned xs = __shfl_sync(0xffffffffu, hu, i);
                    const __half2 xh = *(const __half2*)&xs;
                    acc01 = __hfma2(xh, mh01[i], acc01);
                    acc23 = __hfma2(xh, mh23[i], acc23);
                }
                const float2 p01 = __half22float2(acc01);
                const float2 p23 = __half22float2(acc23);
                float4 o = {p01.x, p01.y, p23.x, p23.y};
                *(float4*)(sPC + par * 1024 + ks * 256 + jq * 4) = o;
            }
        } else {
            // mem warps: 2 columns x half m-range
            const int moff = hh ? 24 : 0;
            const float* wub = sAttn + (s ? (s - 1) * AS : 0) + moff;
            const float* wsb = sAttn + s * AS + moff;
            const float* wrb = sAttn + ((s + 1 < NS) ? (s + 1) : (NS - 1)) * AS + moff;
            float2 ev, av;
            if (s == 0) {
                ev.x = ev.y = av.x = av.y = 0.f;
            } else {
                const float* pc = sPC + parm * 1024;
                float2 pe = *(const float2*)(sm + SM_BE + c2);
                float2 pa = *(const float2*)(sm + SM_BA + c2);
#pragma unroll
                for (int g = 0; g < 4; g++) {
                    const float2 q = *(const float2*)(pc + g * 256 + c2);
                    const float2 r = *(const float2*)(pc + g * 256 + 128 + c2);
                    pe.x += q.x; pe.y += q.y;
                    pa.x += r.x; pa.y += r.y;
                }
                ev.x = sigmoid_fast(pe.x); ev.y = sigmoid_fast(pe.y);
                av.x = tanh_fast(pa.x);    av.y = tanh_fast(pa.y);
            }
            const float nex = -ev.x, ney = -ev.y;
            float2 r0v = {0.f, 0.f}, gv = {0.f, 0.f};
            float cacc = 0.f;

#define MEM2(wum, wsm, wrm, m) { \
    float2 v = *(float2*)(sV + (m) * ND + c2); \
    v.x = fmaf(wum, fmaf(nex, v.x, av.x), v.x); \
    v.y = fmaf(wum, fmaf(ney, v.y, av.y), v.y); \
    *(float2*)(sV + (m) * ND + c2) = v; \
    const float px = (wrm) * v.x, py = (wrm) * v.y; \
    r0v.x += px; r0v.y += py; \
    gv.x = fmaf(wsm, px, gv.x); gv.y = fmaf(wsm, py, gv.y); \
    cacc = fmaf(wrm, wsm, cacc); }

#pragma unroll
            for (int q = 0; q < 6; q++) {
                const float4 wu4 = *(const float4*)(wub + q * 4);
                const float4 ws4 = *(const float4*)(wsb + q * 4);
                const float4 wr4 = *(const float4*)(wrb + q * 4);
                MEM2(wu4.x, ws4.x, wr4.x, moff + q * 4 + 0)
                MEM2(wu4.y, ws4.y, wr4.y, moff + q * 4 + 1)
                MEM2(wu4.z, ws4.z, wr4.z, moff + q * 4 + 2)
                MEM2(wu4.w, ws4.w, wr4.w, moff + q * 4 + 3)
            }
            if (hh) {
                const float2 wu2 = *(const float2*)(wub + 24);
                const float2 ws2 = *(const float2*)(wsb + 24);
                const float2 wr2 = *(const float2*)(wrb + 24);
                MEM2(wu2.x, ws2.x, wr2.x, 48)
                MEM2(wu2.y, ws2.y, wr2.y, 49)
            }
#undef MEM2
            *(float2*)(sm + SM_R0 + parm * 256 + hh * 128 + c2) = r0v;
            *(float2*)(sm + SM_G  + parm * 256 + hh * 128 + c2) = gv;
            if ((u2 & 63) == 0) sm[SM_C + parm * 2 + hh] = cacc;
        }
        __syncthreads();
    }

    // ---- tail: read_out = w_99 . v_100 via the same identity ----
    if (t < ND) {
        const float* pc = sPC + 1024;       // parity of s=99
        float pe = sm[SM_BE + t];
        float pa = sm[SM_BA + t];
#pragma unroll
        for (int g = 0; g < 4; g++) {
            pe += pc[g * 256 + t];
            pa += pc[g * 256 + 128 + t];
        }
        const float e = sigmoid_fast(pe);
        const float a = tanh_fast(pa);
        const float r0 = sm[SM_R0 + t] + sm[SM_R0 + 128 + t];   // parity 0
        const float gg = sm[SM_G + t] + sm[SM_G + 128 + t];
        const float cc = sm[SM_C] + sm[SM_C + 1];
        sRead[t] = fmaf(cc, a, fmaf(-e, gg, r0));
        const int qi = qseq[b * NS + (NS - 1)];
        sUp[t] = emb[qi * ND + t];   // qe_last
    }
    __syncthreads();

    // ---- output head ----
    if (t < 256) {
        const float* pin = (kg < 4) ? sRead : (sUp - ND);
        float4 acc = {0.f, 0.f, 0.f, 0.f};
#pragma unroll
        for (int i = 0; i < 32; i++) {
            const int k = kg * 32 + i;
            const float x = pin[k];
            const float4 wv = *(const float4*)(out_w1 + k * ND + j4);
            acc.x = fmaf(x, wv.x, acc.x);
            acc.y = fmaf(x, wv.y, acc.y);
            acc.z = fmaf(x, wv.z, acc.z);
            acc.w = fmaf(x, wv.w, acc.w);
        }
        *(float4*)(sPA + kg * ND + j4) = acc;
    }
    __syncthreads();
    if (t < ND) {
        float v = out_b1[t];
#pragma unroll
        for (int g = 0; g < 8; g++) v += sPA[g * ND + t];
        sH[t] = fmaxf(v, 0.f) * out_w2[t];
    }
    __syncthreads();
    if (t < 32) {
        float v = sH[t] + sH[t + 32] + sH[t + 64] + sH[t + 96];
#pragma unroll
        for (int o = 16; o; o >>= 1) v += __shfl_xor_sync(0xffffffffu, v, o);
        if (t == 0) out[b] = 1.f / (1.f + __expf(-(v + out_b2[0])));
    }
}

// ---------------------------------------------------------------------------
extern "C" void kernel_launch(void* const* d_in, const int* in_sizes, int n_in,
                              void* d_out, int out_size) {
    const int*   qseq   = (const int*)  d_in[0];
    // d_in[1] = answer_seq (unused by reference)
    const float* emb    = (const float*)d_in[2];
    const float* keym   = (const float*)d_in[3];
    const float* vu_w1  = (const float*)d_in[4];
    const float* vu_b1  = (const float*)d_in[5];
    const float* vu_w2  = (const float*)d_in[6];
    const float* vu_b2  = (const float*)d_in[7];
    const float* er_w   = (const float*)d_in[8];
    const float* er_b   = (const float*)d_in[9];
    const float* ad_w   = (const float*)d_in[10];
    const float* ad_b   = (const float*)d_in[11];
    const float* out_w1 = (const float*)d_in[12];
    const float* out_b1 = (const float*)d_in[13];
    const float* out_w2 = (const float*)d_in[14];
    const float* out_b2 = (const float*)d_in[15];
    float* out = (float*)d_out;

    cudaFuncSetAttribute(fused_kernel,
                         cudaFuncAttributeMaxDynamicSharedMemorySize, SMEM_BYTES);

    combine_kernel<<<ND, 256>>>(vu_w2, vu_b2, er_w, er_b, ad_w, ad_b);
    fused_kernel<<<NB, T, SMEM_BYTES>>>(qseq, emb, keym, vu_w1, vu_b1,
                                        out_w1, out_b1, out_w2, out_b2, out);
}